// round 12
// baseline (speedup 1.0000x reference)
#include <cuda_runtime.h>
#include <cuda_bf16.h>
#include <cstdint>

// ---------------------------------------------------------------------------
// SymbolicFeatureExtractor: per-row (seq_len, unique_count) -> 3 feats -> MLP.
// MLP output depends only on (seq_len, uniq) in [0,128]^2 -> 129x129x32 LUT
// (2.1 MB, L2-resident; inputs/outputs use streaming hints to protect it).
//
// R12: FOUR rows per warp (all 8 input LDG.128 front-batched), processed
// sequentially through one 512-slot per-warp table. pack carries a 2-bit row
// tag: pack = v*512 + row*128 + pos; x = slot^pack; x<128 <=> value AND row
// match (cohort resolved; x==0 member is the unique winner, counts 1).
// Sync discipline (proven R8/R11): one syncwarp after each round's writes;
// none between reads and next writes (benign-misread: a misdirected resolve
// never has x==0, cohort still counted once downstream); row isolation via
// the tail loop's unconditional ballot (warp-convergent, data-dependent on
// completed reads) + the row tag as defense-in-depth. No clears ever.
//
// PDL: build_lut triggers completion after its stores; feat_kernel launches
// programmatically-serialized, runs loads/scatter/count concurrently with
// build_lut, and calls cudaGridDependencySynchronize() (primary completion +
// full visibility) right before the LUT gather.
// ---------------------------------------------------------------------------

#define MAX_LEN 128
#define LUT_DIM 129

__device__ float g_lut[LUT_DIM * LUT_DIM * 32];

#define LUT_PAIRS_PER_WARP 8

__global__ __launch_bounds__(256)
void build_lut_kernel(const float* __restrict__ W1, const float* __restrict__ b1,
                      const float* __restrict__ W2, const float* __restrict__ b2) {
    int warp_in_block = threadIdx.x >> 5;
    int lane = threadIdx.x & 31;
    int base = (blockIdx.x * (blockDim.x >> 5) + warp_in_block) * LUT_PAIRS_PER_WARP;
    if (base < LUT_DIM * LUT_DIM) {
        float w10 = W1[0 * 32 + lane];
        float w11 = W1[1 * 32 + lane];
        float w12 = W1[2 * 32 + lane];
        float bb1 = b1[lane];
        float bb2 = b2[lane];
        float w2c[32];
        #pragma unroll
        for (int k = 0; k < 32; k++) w2c[k] = W2[k * 32 + lane];

        #pragma unroll
        for (int p = 0; p < LUT_PAIRS_PER_WARP; p++) {
            int idx = base + p;
            if (idx >= LUT_DIM * LUT_DIM) break;
            int s = idx / LUT_DIM;
            int u = idx % LUT_DIM;

            float f0 = (float)s * (1.0f / MAX_LEN);
            float f1 = (float)u * (1.0f / MAX_LEN);
            float f2 = (s > 0) ? ((float)u / (float)s) : 0.0f;

            float h = bb1;
            h = fmaf(f0, w10, h);
            h = fmaf(f1, w11, h);
            h = fmaf(f2, w12, h);
            h = fmaxf(h, 0.0f);

            float o = bb2;
            #pragma unroll
            for (int k = 0; k < 32; k++) {
                float hk = __shfl_sync(0xffffffffu, h, k);
                o = fmaf(hk, w2c[k], o);
            }
            g_lut[(size_t)idx * 32 + lane] = fmaxf(o, 0.0f);
        }
    }
#if __CUDA_ARCH__ >= 900
    cudaTriggerProgrammaticLaunchCompletion();
#endif
}

#define WARPS_PER_BLOCK 8
#define ROWS_PER_WARP 4
#define HASH_SLOTS 512      // 16 KB/block

// Count uniques for one row's 4 tokens. row_tag = row<<7 (0,128,256,384).
__device__ __forceinline__ int count_uniques(int* tab, const int4& iv,
                                             const int4& mv, int lane,
                                             int row_tag) {
    int vals[4] = {iv.x, iv.y, iv.z, iv.w};
    bool pend[4] = {mv.x != 0, mv.y != 0, mv.z != 0, mv.w != 0};

    int base_pos = row_tag + lane * 4;
    int pack[4];
    #pragma unroll
    for (int t = 0; t < 4; t++)
        pack[t] = vals[t] * 512 + (base_pos + t);   // (v<<9)|(row<<7)|pos

    int cnt = 0;
    unsigned h[4];

    // round 0: direct-mapped
    #pragma unroll
    for (int t = 0; t < 4; t++) {
        h[t] = (unsigned)vals[t] & (HASH_SLOTS - 1);
        if (pend[t]) tab[h[t]] = pack[t];
    }
    __syncwarp();                      // writes before reads (required)
    #pragma unroll
    for (int t = 0; t < 4; t++) {
        if (pend[t]) {
            int x = tab[h[t]] ^ pack[t];
            if ((unsigned)x < 128u) { pend[t] = false; cnt += (x == 0); }
        }
    }
    // no syncwarp: benign-misread analysis (header)

    // round 1: multiplicative hash, survivors only
    #pragma unroll
    for (int t = 0; t < 4; t++) {
        if (pend[t]) {
            h[t] = ((unsigned)vals[t] * 2654435761u) >> 23;
            tab[h[t]] = pack[t];
        }
    }
    __syncwarp();                      // writes before reads (required)
    #pragma unroll
    for (int t = 0; t < 4; t++) {
        if (pend[t]) {
            int x = tab[h[t]] ^ pack[t];
            if ((unsigned)x < 128u) { pend[t] = false; cnt += (x == 0); }
        }
    }

    // tail: smem-free cohort broadcast (exact; ~0 iterations typical).
    // The unconditional ballot also row-isolates successive calls.
    while (true) {
        bool any = pend[0] | pend[1] | pend[2] | pend[3];
        unsigned m = __ballot_sync(0xffffffffu, any);
        if (!m) break;
        int leader = __ffs(m) - 1;
        int myv = pend[0] ? vals[0] : pend[1] ? vals[1]
                : pend[2] ? vals[2] : vals[3];
        int lv = __shfl_sync(0xffffffffu, myv, leader);
        cnt += (lane == leader);
        #pragma unroll
        for (int t = 0; t < 4; t++)
            pend[t] &= (vals[t] != lv);
    }
    return cnt;
}

__global__ __launch_bounds__(WARPS_PER_BLOCK * 32, 4)
void feat_kernel(const int* __restrict__ ids, const int* __restrict__ mask,
                 float* __restrict__ out, int B) {
    __shared__ int table[WARPS_PER_BLOCK][HASH_SLOTS];

    int w    = threadIdx.x >> 5;
    int lane = threadIdx.x & 31;
    int row0 = (blockIdx.x * WARPS_PER_BLOCK + w) * ROWS_PER_WARP;
    if (row0 < B) {
        int* tab = table[w];

        // Front-batch all 8 input loads (MLP 8, streaming to protect L2 LUT).
        int4 iv[ROWS_PER_WARP], mv[ROWS_PER_WARP];
        #pragma unroll
        for (int r = 0; r < ROWS_PER_WARP; r++) {
            int row = row0 + r;
            if (row < B) {
                iv[r] = __ldcs((const int4*)(ids  + (size_t)row * MAX_LEN) + lane);
                mv[r] = __ldcs((const int4*)(mask + (size_t)row * MAX_LEN) + lane);
            } else {
                iv[r] = make_int4(0, 0, 0, 0);
                mv[r] = make_int4(0, 0, 0, 0);
            }
        }

        int idx[ROWS_PER_WARP];
        #pragma unroll
        for (int r = 0; r < ROWS_PER_WARP; r++) {
            int seq = mv[r].x + mv[r].y + mv[r].z + mv[r].w;
            int cnt = count_uniques(tab, iv[r], mv[r], lane, r << 7);
            // LUT index is linear in per-lane partials: one REDUX per row.
            idx[r] = __reduce_add_sync(0xffffffffu, seq * LUT_DIM + cnt);
        }

#if __CUDA_ARCH__ >= 900
        cudaGridDependencySynchronize();   // LUT writes visible from here
#endif

        #pragma unroll
        for (int r = 0; r < ROWS_PER_WARP; r++) {
            float v = g_lut[(size_t)idx[r] * 32 + lane];
            if (row0 + r < B)
                __stcs(&out[(size_t)(row0 + r) * 32 + lane], v);
        }
    } else {
#if __CUDA_ARCH__ >= 900
        cudaGridDependencySynchronize();
#endif
    }
}

extern "C" void kernel_launch(void* const* d_in, const int* in_sizes, int n_in,
                              void* d_out, int out_size) {
    const int*   ids  = (const int*)d_in[0];
    const int*   mask = (const int*)d_in[1];
    const float* W1   = (const float*)d_in[2];
    const float* b1   = (const float*)d_in[3];
    const float* W2   = (const float*)d_in[4];
    const float* b2   = (const float*)d_in[5];
    float* out = (float*)d_out;

    int B = in_sizes[0] / MAX_LEN;

    int lut_pairs  = LUT_DIM * LUT_DIM;
    int pairs_per_block = 8 * LUT_PAIRS_PER_WARP;
    int lut_blocks = (lut_pairs + pairs_per_block - 1) / pairs_per_block;
    build_lut_kernel<<<lut_blocks, 256>>>(W1, b1, W2, b2);

    int rows_per_block = WARPS_PER_BLOCK * ROWS_PER_WARP;
    int blocks = (B + rows_per_block - 1) / rows_per_block;

    // PDL: feat_kernel may launch while build_lut runs; the in-kernel
    // cudaGridDependencySynchronize() orders the LUT gather after it.
    cudaLaunchConfig_t cfg = {};
    cfg.gridDim  = dim3(blocks, 1, 1);
    cfg.blockDim = dim3(WARPS_PER_BLOCK * 32, 1, 1);
    cudaLaunchAttribute attrs[1];
    attrs[0].id = cudaLaunchAttributeProgrammaticStreamSerialization;
    attrs[0].val.programmaticStreamSerializationAllowed = 1;
    cfg.attrs = attrs;
    cfg.numAttrs = 1;
    cudaLaunchKernelEx(&cfg, feat_kernel, ids, mask, out, B);
}

// round 13
// speedup vs baseline: 1.0672x; 1.0672x over previous
#include <cuda_runtime.h>
#include <cuda_bf16.h>
#include <cstdint>

// ---------------------------------------------------------------------------
// SymbolicFeatureExtractor: per-row (seq_len, unique_count) -> 3 feats -> MLP.
// MLP output depends only on (seq_len, uniq) in [0,128]^2 -> 129x129x32 LUT
// (2.1 MB, L2-resident; inputs/outputs use streaming hints to protect it).
//
// R13 = R11 feat kernel (two rows per warp -- the measured ILP/occupancy
// optimum: 39 regs, ~65% occ) + R12's PDL overlap of build_lut with feat's
// load/scatter/count front half.
//
// Unique counting (proven R8/R11): 512-slot per-warp table, no clears.
// pack = v*256 + row*128 + pos; x = slot^pack; x<128 <=> value AND row match
// (cohort resolved; the x==0 member is the unique winner, counts 1).
// One syncwarp after each round's writes; none between reads and next
// writes (benign-misread: a misdirected resolve never has x==0; cohort is
// still counted exactly once by the round-1 winner or the exact tail loop).
// Row isolation via the tail loop's unconditional ballot (warp-convergent,
// data-dependent on completed reads) + row bit as defense-in-depth.
//
// PDL: build_lut triggers completion after its stores; feat_kernel launches
// programmatically-serialized and calls cudaGridDependencySynchronize()
// right before the LUT gather (primary completion + visibility guaranteed).
// ---------------------------------------------------------------------------

#define MAX_LEN 128
#define LUT_DIM 129

__device__ float g_lut[LUT_DIM * LUT_DIM * 32];

#define LUT_PAIRS_PER_WARP 8

__global__ __launch_bounds__(256)
void build_lut_kernel(const float* __restrict__ W1, const float* __restrict__ b1,
                      const float* __restrict__ W2, const float* __restrict__ b2) {
    int warp_in_block = threadIdx.x >> 5;
    int lane = threadIdx.x & 31;
    int base = (blockIdx.x * (blockDim.x >> 5) + warp_in_block) * LUT_PAIRS_PER_WARP;
    if (base < LUT_DIM * LUT_DIM) {
        float w10 = W1[0 * 32 + lane];
        float w11 = W1[1 * 32 + lane];
        float w12 = W1[2 * 32 + lane];
        float bb1 = b1[lane];
        float bb2 = b2[lane];
        float w2c[32];
        #pragma unroll
        for (int k = 0; k < 32; k++) w2c[k] = W2[k * 32 + lane];

        #pragma unroll
        for (int p = 0; p < LUT_PAIRS_PER_WARP; p++) {
            int idx = base + p;
            if (idx >= LUT_DIM * LUT_DIM) break;
            int s = idx / LUT_DIM;
            int u = idx % LUT_DIM;

            float f0 = (float)s * (1.0f / MAX_LEN);
            float f1 = (float)u * (1.0f / MAX_LEN);
            float f2 = (s > 0) ? ((float)u / (float)s) : 0.0f;

            float h = bb1;
            h = fmaf(f0, w10, h);
            h = fmaf(f1, w11, h);
            h = fmaf(f2, w12, h);
            h = fmaxf(h, 0.0f);

            float o = bb2;
            #pragma unroll
            for (int k = 0; k < 32; k++) {
                float hk = __shfl_sync(0xffffffffu, h, k);
                o = fmaf(hk, w2c[k], o);
            }
            g_lut[(size_t)idx * 32 + lane] = fmaxf(o, 0.0f);
        }
    }
#if __CUDA_ARCH__ >= 900
    cudaTriggerProgrammaticLaunchCompletion();
#endif
}

#define WARPS_PER_BLOCK 8
#define ROWS_PER_WARP 2
#define HASH_SLOTS 512      // 16 KB/block

// Count uniques for one row's 4 tokens. row_tag is 0 or 128 (row bit).
__device__ __forceinline__ int count_uniques(int* tab, const int4& iv,
                                             const int4& mv, int lane,
                                             int row_tag) {
    int vals[4] = {iv.x, iv.y, iv.z, iv.w};
    bool pend[4] = {mv.x != 0, mv.y != 0, mv.z != 0, mv.w != 0};

    int base_pos = row_tag + lane * 4;
    int pack[4];
    #pragma unroll
    for (int t = 0; t < 4; t++)
        pack[t] = vals[t] * 256 + (base_pos + t);   // (v<<8)|(row<<7)|pos

    int cnt = 0;
    unsigned h[4];

    // round 0: direct-mapped
    #pragma unroll
    for (int t = 0; t < 4; t++) {
        h[t] = (unsigned)vals[t] & (HASH_SLOTS - 1);
        if (pend[t]) tab[h[t]] = pack[t];
    }
    __syncwarp();                      // writes before reads (required)
    #pragma unroll
    for (int t = 0; t < 4; t++) {
        if (pend[t]) {
            int x = tab[h[t]] ^ pack[t];
            if ((unsigned)x < 128u) { pend[t] = false; cnt += (x == 0); }
        }
    }
    // no syncwarp: benign-misread analysis (header)

    // round 1: multiplicative hash, survivors only
    #pragma unroll
    for (int t = 0; t < 4; t++) {
        if (pend[t]) {
            h[t] = ((unsigned)vals[t] * 2654435761u) >> 23;
            tab[h[t]] = pack[t];
        }
    }
    __syncwarp();                      // writes before reads (required)
    #pragma unroll
    for (int t = 0; t < 4; t++) {
        if (pend[t]) {
            int x = tab[h[t]] ^ pack[t];
            if ((unsigned)x < 128u) { pend[t] = false; cnt += (x == 0); }
        }
    }

    // tail: smem-free cohort broadcast (exact; ~0 iterations typical).
    // The unconditional ballot also row-isolates successive calls.
    while (true) {
        bool any = pend[0] | pend[1] | pend[2] | pend[3];
        unsigned m = __ballot_sync(0xffffffffu, any);
        if (!m) break;
        int leader = __ffs(m) - 1;
        int myv = pend[0] ? vals[0] : pend[1] ? vals[1]
                : pend[2] ? vals[2] : vals[3];
        int lv = __shfl_sync(0xffffffffu, myv, leader);
        cnt += (lane == leader);
        #pragma unroll
        for (int t = 0; t < 4; t++)
            pend[t] &= (vals[t] != lv);
    }
    return cnt;
}

__global__ __launch_bounds__(WARPS_PER_BLOCK * 32, 6)
void feat_kernel(const int* __restrict__ ids, const int* __restrict__ mask,
                 float* __restrict__ out, int B) {
    __shared__ int table[WARPS_PER_BLOCK][HASH_SLOTS];

    int w    = threadIdx.x >> 5;
    int lane = threadIdx.x & 31;
    int row0 = (blockIdx.x * WARPS_PER_BLOCK + w) * ROWS_PER_WARP;
    if (row0 < B) {
        int row1 = row0 + 1;
        bool has1 = row1 < B;
        int* tab = table[w];

        // Front-batch all 4 input loads (MLP 4, streaming to protect L2 LUT).
        const int4* id0 = (const int4*)(ids  + (size_t)row0 * MAX_LEN);
        const int4* mk0 = (const int4*)(mask + (size_t)row0 * MAX_LEN);
        const int4* id1 = (const int4*)(ids  + (size_t)row1 * MAX_LEN);
        const int4* mk1 = (const int4*)(mask + (size_t)row1 * MAX_LEN);
        int4 iv0 = __ldcs(id0 + lane);
        int4 mv0 = __ldcs(mk0 + lane);
        int4 iv1, mv1;
        if (has1) { iv1 = __ldcs(id1 + lane); mv1 = __ldcs(mk1 + lane); }
        else      { iv1 = make_int4(0,0,0,0); mv1 = make_int4(0,0,0,0); }

        int seq0 = mv0.x + mv0.y + mv0.z + mv0.w;
        int seq1 = mv1.x + mv1.y + mv1.z + mv1.w;

        int cnt0 = count_uniques(tab, iv0, mv0, lane, 0);
        int cnt1 = count_uniques(tab, iv1, mv1, lane, 128);

        // LUT index is linear in per-lane partials: one REDUX per row.
        int idx0 = __reduce_add_sync(0xffffffffu, seq0 * LUT_DIM + cnt0);
        int idx1 = __reduce_add_sync(0xffffffffu, seq1 * LUT_DIM + cnt1);

#if __CUDA_ARCH__ >= 900
        cudaGridDependencySynchronize();   // LUT writes visible from here
#endif

        float v0 = g_lut[(size_t)idx0 * 32 + lane];
        float v1 = g_lut[(size_t)idx1 * 32 + lane];
        __stcs(&out[(size_t)row0 * 32 + lane], v0);
        if (has1) __stcs(&out[(size_t)row1 * 32 + lane], v1);
    } else {
#if __CUDA_ARCH__ >= 900
        cudaGridDependencySynchronize();
#endif
    }
}

extern "C" void kernel_launch(void* const* d_in, const int* in_sizes, int n_in,
                              void* d_out, int out_size) {
    const int*   ids  = (const int*)d_in[0];
    const int*   mask = (const int*)d_in[1];
    const float* W1   = (const float*)d_in[2];
    const float* b1   = (const float*)d_in[3];
    const float* W2   = (const float*)d_in[4];
    const float* b2   = (const float*)d_in[5];
    float* out = (float*)d_out;

    int B = in_sizes[0] / MAX_LEN;

    int lut_pairs  = LUT_DIM * LUT_DIM;
    int pairs_per_block = 8 * LUT_PAIRS_PER_WARP;
    int lut_blocks = (lut_pairs + pairs_per_block - 1) / pairs_per_block;
    build_lut_kernel<<<lut_blocks, 256>>>(W1, b1, W2, b2);

    int rows_per_block = WARPS_PER_BLOCK * ROWS_PER_WARP;
    int blocks = (B + rows_per_block - 1) / rows_per_block;

    // PDL: feat_kernel may launch while build_lut runs; the in-kernel
    // cudaGridDependencySynchronize() orders the LUT gather after it.
    cudaLaunchConfig_t cfg = {};
    cfg.gridDim  = dim3(blocks, 1, 1);
    cfg.blockDim = dim3(WARPS_PER_BLOCK * 32, 1, 1);
    cudaLaunchAttribute attrs[1];
    attrs[0].id = cudaLaunchAttributeProgrammaticStreamSerialization;
    attrs[0].val.programmaticStreamSerializationAllowed = 1;
    cfg.attrs = attrs;
    cfg.numAttrs = 1;
    cudaLaunchKernelEx(&cfg, feat_kernel, ids, mask, out, B);
}